// round 6
// baseline (speedup 1.0000x reference)
#include <cuda_runtime.h>
#include <cuda_fp16.h>
#include <math.h>
#include <stdint.h>

// ---------------------------------------------------------------------------
// fkopt_net round 6: fp16x3 mma.sync GEMM.
//  L2/L3: tile 128x64, grid 2048 CTAs (1.2% wave tail), 4-stage x 24KB pipeline.
//  L4:    tile 128x128, 3-stage x 32KB (validated shape).
//  2 CTAs/SM everywhere; smem-staged epilogues with bulk S2G.
// ---------------------------------------------------------------------------

#define BATCH 16384
#define KDIM  1024
#define NEG_SLOPE 0.01f

__device__ __align__(1024) __half g_a0h[BATCH * KDIM];
__device__ __align__(1024) __half g_a0l[BATCH * KDIM];
__device__ __align__(1024) __half g_a1h[BATCH * KDIM];
__device__ __align__(1024) __half g_a1l[BATCH * KDIM];
__device__ __align__(1024) __half g_w2h[KDIM * KDIM];
__device__ __align__(1024) __half g_w2l[KDIM * KDIM];
__device__ __align__(1024) __half g_w3h[KDIM * KDIM];
__device__ __align__(1024) __half g_w3l[KDIM * KDIM];
__device__ __align__(1024) __half g_w4h[256 * KDIM];
__device__ __align__(1024) __half g_w4l[256 * KDIM];
__device__ __align__(1024) float g_joints[BATCH * 256];

// ---------------- PTX helpers ----------------------------------------------
__device__ __forceinline__ uint32_t smem_u32(const void* p) {
    uint32_t a;
    asm("{ .reg .u64 t; cvta.to.shared.u64 t, %1; cvt.u32.u64 %0, t; }"
        : "=r"(a) : "l"(p));
    return a;
}
__device__ __forceinline__ void mbar_init(uint32_t a, uint32_t c) {
    asm volatile("mbarrier.init.shared.b64 [%0], %1;" :: "r"(a), "r"(c) : "memory");
}
__device__ __forceinline__ void mbar_expect(uint32_t a, uint32_t tx) {
    asm volatile("mbarrier.arrive.expect_tx.shared.b64 _, [%0], %1;"
                 :: "r"(a), "r"(tx) : "memory");
}
__device__ __forceinline__ void mbar_wait(uint32_t a, uint32_t ph) {
    asm volatile(
        "{\n\t.reg .pred P;\n\t"
        "WL_%=:\n\t"
        "mbarrier.try_wait.parity.acquire.cta.shared::cta.b64 P, [%0], %1, 0x989680;\n\t"
        "@P bra.uni WD_%=;\n\t"
        "bra.uni WL_%=;\n\t"
        "WD_%=:\n\t}"
        :: "r"(a), "r"(ph) : "memory");
}
__device__ __forceinline__ void bulk_g2s(uint32_t dst, const void* src,
                                         uint32_t bytes, uint32_t mbar) {
    asm volatile(
        "cp.async.bulk.shared::cluster.global.mbarrier::complete_tx::bytes "
        "[%0], [%1], %2, [%3];"
        :: "r"(dst), "l"(src), "r"(bytes), "r"(mbar) : "memory");
}
__device__ __forceinline__ void bulk_s2g(void* dst, uint32_t src, uint32_t bytes) {
    asm volatile(
        "cp.async.bulk.global.shared::cta.bulk_group [%0], [%1], %2;"
        :: "l"(dst), "r"(src), "r"(bytes) : "memory");
}

#define LDSM4(r, a)                                                              \
    asm volatile("ldmatrix.sync.aligned.m8n8.x4.shared.b16 {%0,%1,%2,%3}, [%4];" \
                 : "=r"((r)[0]), "=r"((r)[1]), "=r"((r)[2]), "=r"((r)[3])        \
                 : "r"(a))
#define LDSM2(r, a)                                                              \
    asm volatile("ldmatrix.sync.aligned.m8n8.x2.shared.b16 {%0,%1}, [%2];"       \
                 : "=r"((r)[0]), "=r"((r)[1]) : "r"(a))
#define MMA16816(d, a, b)                                                        \
    asm volatile("mma.sync.aligned.m16n8k16.row.col.f32.f16.f16.f32 "            \
                 "{%0,%1,%2,%3}, {%4,%5,%6,%7}, {%8,%9}, {%0,%1,%2,%3};"         \
                 : "+f"((d)[0]), "+f"((d)[1]), "+f"((d)[2]), "+f"((d)[3])        \
                 : "r"((a)[0]), "r"((a)[1]), "r"((a)[2]), "r"((a)[3]),           \
                   "r"((b)[0]), "r"((b)[1]))

// tile byte-offset swizzle: off = row*64 + col*2 (32 fp16 cols per row)
__device__ __forceinline__ uint32_t swz(uint32_t off) {
    return off ^ (((off >> 7) & 3u) << 4);
}
__device__ __forceinline__ void split_h(float v, __half& h, __half& l) {
    h = __float2half_rn(v);
    l = __float2half_rn(v - __half2float(h));
}
__device__ __forceinline__ uint32_t pack_h2(__half a, __half b) {
    return ((uint32_t)__half_as_ushort(b) << 16) | (uint32_t)__half_as_ushort(a);
}

// ---------------------------------------------------------------------------
// Layer 1 producer (validated)
// ---------------------------------------------------------------------------
__global__ __launch_bounds__(256) void layer1_kernel(
    const float* __restrict__ x, const float* __restrict__ W1,
    const float* __restrict__ b1,
    __half* __restrict__ Ohi, __half* __restrict__ Olo)
{
    int idx = blockIdx.x * 256 + threadIdx.x;
    int n0 = (idx & 127) * 8;
    int m  = idx >> 7;
    float x0 = __ldg(x + m * 3 + 0);
    float x1 = __ldg(x + m * 3 + 1);
    float x2 = __ldg(x + m * 3 + 2);

    uint32_t hw[4], lw[4];
    #pragma unroll
    for (int p = 0; p < 4; p++) {
        int n = n0 + 2 * p;
        float v0 = __ldg(b1 + n) + x0 * __ldg(W1 + n) +
                   x1 * __ldg(W1 + 1024 + n) + x2 * __ldg(W1 + 2048 + n);
        float v1 = __ldg(b1 + n + 1) + x0 * __ldg(W1 + n + 1) +
                   x1 * __ldg(W1 + 1024 + n + 1) + x2 * __ldg(W1 + 2048 + n + 1);
        v0 = (v0 >= 0.0f) ? v0 : NEG_SLOPE * v0;
        v1 = (v1 >= 0.0f) ? v1 : NEG_SLOPE * v1;
        __half h0, l0, h1, l1;
        split_h(v0, h0, l0); split_h(v1, h1, l1);
        hw[p] = pack_h2(h0, h1);
        lw[p] = pack_h2(l0, l1);
    }
    size_t tile = (size_t)(m >> 7) * 32 + (n0 >> 5);
    uint32_t off = swz((uint32_t)(m & 127) * 64 + (uint32_t)(n0 & 31) * 2);
    *(uint4*)((char*)Ohi + tile * 8192 + off) = make_uint4(hw[0], hw[1], hw[2], hw[3]);
    *(uint4*)((char*)Olo + tile * 8192 + off) = make_uint4(lw[0], lw[1], lw[2], lw[3]);
}

// ---------------------------------------------------------------------------
// Weight convert+transpose producer (validated)
// ---------------------------------------------------------------------------
__global__ __launch_bounds__(256) void wconv_kernel(
    const float* __restrict__ W,
    __half* __restrict__ Ohi, __half* __restrict__ Olo, int N)
{
    int idx = blockIdx.x * 256 + threadIdx.x;
    int n  = idx % N;
    int k0 = (idx / N) * 8;
    uint32_t hw[4], lw[4];
    #pragma unroll
    for (int p = 0; p < 4; p++) {
        float v0 = __ldg(W + (size_t)(k0 + 2 * p) * N + n);
        float v1 = __ldg(W + (size_t)(k0 + 2 * p + 1) * N + n);
        __half h0, l0, h1, l1;
        split_h(v0, h0, l0); split_h(v1, h1, l1);
        hw[p] = pack_h2(h0, h1);
        lw[p] = pack_h2(l0, l1);
    }
    size_t tile = (size_t)(n >> 7) * 32 + (k0 >> 5);
    uint32_t off = swz((uint32_t)(n & 127) * 64 + (uint32_t)(k0 & 31) * 2);
    *(uint4*)((char*)Ohi + tile * 8192 + off) = make_uint4(hw[0], hw[1], hw[2], hw[3]);
    *(uint4*)((char*)Olo + tile * 8192 + off) = make_uint4(lw[0], lw[1], lw[2], lw[3]);
}

// ---------------------------------------------------------------------------
// GEMM 128x64: C = leaky(A @ W + bias), fp16x3.  K=1024, BK=32 (32 chunks),
// 4-stage x 24KB pipeline (Ah8K Al8K Bh4K Bl4K), 2 CTAs/SM.
// 8 warps, warp tile 32x32. Output re-split hi/lo into tiled layout.
// ---------------------------------------------------------------------------
__global__ __launch_bounds__(256, 2) void gemm64_kernel(
    const __half* __restrict__ Ahg, const __half* __restrict__ Alg,
    const __half* __restrict__ Bhg, const __half* __restrict__ Blg,
    const float* __restrict__ bias,
    __half* __restrict__ Ohi, __half* __restrict__ Olo, int Ntot)
{
    constexpr int NC = 32;
    constexpr uint32_t STAGE = 24576;
    __shared__ __align__(8) uint64_t bar_full[4];
    extern __shared__ char dsm[];
    const uint32_t sbase = (smem_u32(dsm) + 1023) & ~1023u;

    const int tid = threadIdx.x, lane = tid & 31, wid = tid >> 5;
    const int mb = blockIdx.y, nb = blockIdx.x;
    const int wm = (wid & 3) * 32;
    const int wn = (wid >> 2) * 32;

    if (tid == 0)
        for (int s = 0; s < 4; s++) mbar_init(smem_u32(&bar_full[s]), 1);
    __syncthreads();

    const char* Ah = (const char*)Ahg + (size_t)mb * 32 * 8192;
    const char* Al = (const char*)Alg + (size_t)mb * 32 * 8192;
    const char* Bh = (const char*)Bhg + (size_t)(nb >> 1) * 32 * 8192 + (size_t)(nb & 1) * 4096;
    const char* Bl = (const char*)Blg + (size_t)(nb >> 1) * 32 * 8192 + (size_t)(nb & 1) * 4096;

    // prologue: stages 0..2
    if (tid == 0) {
        #pragma unroll
        for (int c = 0; c < 3; c++) {
            uint32_t fb = smem_u32(&bar_full[c]);
            mbar_expect(fb, STAGE);
            uint32_t d = sbase + c * STAGE;
            bulk_g2s(d,         Ah + (size_t)c * 8192, 8192, fb);
            bulk_g2s(d + 8192,  Al + (size_t)c * 8192, 8192, fb);
            bulk_g2s(d + 16384, Bh + (size_t)c * 8192, 4096, fb);
            bulk_g2s(d + 20480, Bl + (size_t)c * 8192, 4096, fb);
        }
    }

    // ldmatrix addressing (A tile 8KB: 128 rows x 64B; B tile 4KB: 64 rows x 64B)
    const int rowA = wm + (lane & 15);
    const uint32_t xa = (rowA >> 1) & 3;
    const uint32_t offA = (uint32_t)rowA * 64;
    const uint32_t cA[2] = { (((uint32_t)(lane >> 4) + 0) ^ xa) * 16,
                             (((uint32_t)(lane >> 4) + 2) ^ xa) * 16 };
    const int rowB = wn + (lane & 7);
    const uint32_t xb = (rowB >> 1) & 3;
    const uint32_t offB = (uint32_t)rowB * 64;
    const uint32_t cB[2] = { ((((uint32_t)(lane >> 3) & 1) + 0) ^ xb) * 16,
                             ((((uint32_t)(lane >> 3) & 1) + 2) ^ xb) * 16 };

    float acc[2][4][4];
    #pragma unroll
    for (int i = 0; i < 2; i++)
        #pragma unroll
        for (int j = 0; j < 4; j++)
            #pragma unroll
            for (int r = 0; r < 4; r++) acc[i][j][r] = 0.0f;

    #pragma unroll 1
    for (int c = 0; c < NC; c++) {
        if (tid == 0 && c + 3 < NC) {
            int s = (c + 3) & 3;
            uint32_t fb = smem_u32(&bar_full[s]);
            mbar_expect(fb, STAGE);
            uint32_t d = sbase + s * STAGE;
            bulk_g2s(d,         Ah + (size_t)(c + 3) * 8192, 8192, fb);
            bulk_g2s(d + 8192,  Al + (size_t)(c + 3) * 8192, 8192, fb);
            bulk_g2s(d + 16384, Bh + (size_t)(c + 3) * 8192, 4096, fb);
            bulk_g2s(d + 20480, Bl + (size_t)(c + 3) * 8192, 4096, fb);
        }
        mbar_wait(smem_u32(&bar_full[c & 3]), (c >> 2) & 1);

        const uint32_t sb = sbase + (c & 3) * STAGE;
        #pragma unroll
        for (int kk = 0; kk < 2; kk++) {
            const uint32_t ca = cA[kk], cb = cB[kk];
            uint32_t ah[2][4], al[2][4];
            #pragma unroll
            for (int mi = 0; mi < 2; mi++) {
                LDSM4(ah[mi], sb + offA + mi * 1024 + ca);
                LDSM4(al[mi], sb + 8192 + offA + mi * 1024 + ca);
            }
            #pragma unroll
            for (int ni = 0; ni < 4; ni++) {
                uint32_t bh[2], bl[2];
                LDSM2(bh, sb + 16384 + offB + ni * 512 + cb);
                LDSM2(bl, sb + 20480 + offB + ni * 512 + cb);
                #pragma unroll
                for (int mi = 0; mi < 2; mi++) MMA16816(acc[mi][ni], ah[mi], bh);
                #pragma unroll
                for (int mi = 0; mi < 2; mi++) MMA16816(acc[mi][ni], al[mi], bh);
                #pragma unroll
                for (int mi = 0; mi < 2; mi++) MMA16816(acc[mi][ni], ah[mi], bl);
            }
        }
        __syncthreads();
    }

    // ---------------- epilogue: stage 2 hi + 2 lo tiles (32KB), bulk S2G ----
    const uint32_t chi = sbase, clo = sbase + 16384;
    #pragma unroll
    for (int mi = 0; mi < 2; mi++) {
        #pragma unroll
        for (int ni = 0; ni < 4; ni++) {
            const int nl = wn + ni * 8 + 2 * (lane & 3);   // 0..63
            const int rl = wm + mi * 16 + (lane >> 2);      // 0..127
            float2 bv = *(const float2*)(bias + nb * 64 + nl);
            float v0 = acc[mi][ni][0] + bv.x;
            float v1 = acc[mi][ni][1] + bv.y;
            float v2 = acc[mi][ni][2] + bv.x;
            float v3 = acc[mi][ni][3] + bv.y;
            v0 = (v0 >= 0.0f) ? v0 : NEG_SLOPE * v0;
            v1 = (v1 >= 0.0f) ? v1 : NEG_SLOPE * v1;
            v2 = (v2 >= 0.0f) ? v2 : NEG_SLOPE * v2;
            v3 = (v3 >= 0.0f) ? v3 : NEG_SLOPE * v3;
            __half h0, l0, h1, l1, h2, l2, h3, l3;
            split_h(v0, h0, l0); split_h(v1, h1, l1);
            split_h(v2, h2, l2); split_h(v3, h3, l3);
            const uint32_t tb = (uint32_t)(nl >> 5) * 8192;
            const uint32_t off = swz((uint32_t)rl * 64 + (uint32_t)(nl & 31) * 2);
            asm volatile("st.shared.b32 [%0], %1;" :: "r"(chi + tb + off),       "r"(pack_h2(h0, h1)) : "memory");
            asm volatile("st.shared.b32 [%0], %1;" :: "r"(chi + tb + off + 512), "r"(pack_h2(h2, h3)) : "memory");
            asm volatile("st.shared.b32 [%0], %1;" :: "r"(clo + tb + off),       "r"(pack_h2(l0, l1)) : "memory");
            asm volatile("st.shared.b32 [%0], %1;" :: "r"(clo + tb + off + 512), "r"(pack_h2(l2, l3)) : "memory");
        }
    }
    __syncthreads();
    if (tid == 0) {
        asm volatile("fence.proxy.async;" ::: "memory");
        const size_t tbase = (size_t)mb * (Ntot / 32) + (size_t)nb * 2;
        #pragma unroll
        for (int t = 0; t < 2; t++) {
            bulk_s2g((char*)Ohi + (tbase + t) * 8192, chi + t * 8192, 8192);
            bulk_s2g((char*)Olo + (tbase + t) * 8192, clo + t * 8192, 8192);
        }
        asm volatile("cp.async.bulk.commit_group;" ::: "memory");
        asm volatile("cp.async.bulk.wait_group 0;" ::: "memory");
    }
}

// ---------------------------------------------------------------------------
// GEMM 128x128 (L4): C = tanh(A @ W + bias) fp32 out. 3-stage x 32KB.
// ---------------------------------------------------------------------------
__global__ __launch_bounds__(256, 2) void gemm128_kernel(
    const __half* __restrict__ Ahg, const __half* __restrict__ Alg,
    const __half* __restrict__ Bhg, const __half* __restrict__ Blg,
    const float* __restrict__ bias,
    float* __restrict__ Of, int Ntot)
{
    constexpr int NC = 32;
    constexpr uint32_t STAGE = 32768;
    __shared__ __align__(8) uint64_t bar_full[3];
    extern __shared__ char dsm[];
    const uint32_t sbase = (smem_u32(dsm) + 1023) & ~1023u;

    const int tid = threadIdx.x, lane = tid & 31, wid = tid >> 5;
    const int mb = blockIdx.y, nb = blockIdx.x;
    const int wm = (wid & 1) * 64;
    const int wn = (wid >> 1) * 32;

    if (tid == 0)
        for (int s = 0; s < 3; s++) mbar_init(smem_u32(&bar_full[s]), 1);
    __syncthreads();

    const char* Ah = (const char*)Ahg + (size_t)mb * 32 * 8192;
    const char* Al = (const char*)Alg + (size_t)mb * 32 * 8192;
    const char* Bh = (const char*)Bhg + (size_t)nb * 32 * 8192;
    const char* Bl = (const char*)Blg + (size_t)nb * 32 * 8192;

    if (tid == 0) {
        #pragma unroll
        for (int c = 0; c < 2; c++) {
            uint32_t fb = smem_u32(&bar_full[c]);
            mbar_expect(fb, STAGE);
            uint32_t d = sbase + c * STAGE;
            bulk_g2s(d,         Ah + (size_t)c * 8192, 8192, fb);
            bulk_g2s(d + 8192,  Al + (size_t)c * 8192, 8192, fb);
            bulk_g2s(d + 16384, Bh + (size_t)c * 8192, 8192, fb);
            bulk_g2s(d + 24576, Bl + (size_t)c * 8192, 8192, fb);
        }
    }

    const int rowA = wm + (lane & 15);
    const uint32_t xa = (rowA >> 1) & 3;
    const uint32_t offA = (uint32_t)rowA * 64;
    const uint32_t cA[2] = { (((uint32_t)(lane >> 4) + 0) ^ xa) * 16,
                             (((uint32_t)(lane >> 4) + 2) ^ xa) * 16 };
    const int rowB = wn + (lane & 7);
    const uint32_t xb = (rowB >> 1) & 3;
    const uint32_t offB = (uint32_t)rowB * 64;
    const uint32_t cB[2] = { ((((uint32_t)(lane >> 3) & 1) + 0) ^ xb) * 16,
                             ((((uint32_t)(lane >> 3) & 1) + 2) ^ xb) * 16 };

    float acc[4][4][4];
    #pragma unroll
    for (int i = 0; i < 4; i++)
        #pragma unroll
        for (int j = 0; j < 4; j++)
            #pragma unroll
            for (int r = 0; r < 4; r++) acc[i][j][r] = 0.0f;

    #pragma unroll 1
    for (int c = 0; c < NC; c++) {
        if (tid == 0 && c + 2 < NC) {
            int s = (c + 2) % 3;
            uint32_t fb = smem_u32(&bar_full[s]);
            mbar_expect(fb, STAGE);
            uint32_t d = sbase + s * STAGE;
            bulk_g2s(d,         Ah + (size_t)(c + 2) * 8192, 8192, fb);
            bulk_g2s(d + 8192,  Al + (size_t)(c + 2) * 8192, 8192, fb);
            bulk_g2s(d + 16384, Bh + (size_t)(c + 2) * 8192, 8192, fb);
            bulk_g2s(d + 24576, Bl + (size_t)(c + 2) * 8192, 8192, fb);
        }
        mbar_wait(smem_u32(&bar_full[c % 3]), (c / 3) & 1);

        const uint32_t sb = sbase + (c % 3) * STAGE;
        #pragma unroll
        for (int kk = 0; kk < 2; kk++) {
            const uint32_t ca = cA[kk], cb = cB[kk];
            uint32_t ah[4][4], al[4][4];
            #pragma unroll
            for (int mi = 0; mi < 4; mi++) {
                LDSM4(ah[mi], sb + offA + mi * 1024 + ca);
                LDSM4(al[mi], sb + 8192 + offA + mi * 1024 + ca);
            }
            #pragma unroll
            for (int ni = 0; ni < 4; ni++) {
                uint32_t bh[2], bl[2];
                LDSM2(bh, sb + 16384 + offB + ni * 512 + cb);
                LDSM2(bl, sb + 24576 + offB + ni * 512 + cb);
                #pragma unroll
                for (int mi = 0; mi < 4; mi++) MMA16816(acc[mi][ni], ah[mi], bh);
                #pragma unroll
                for (int mi = 0; mi < 4; mi++) MMA16816(acc[mi][ni], al[mi], bh);
                #pragma unroll
                for (int mi = 0; mi < 4; mi++) MMA16816(acc[mi][ni], ah[mi], bl);
            }
        }
        __syncthreads();
    }

    // epilogue: fp32 tile staged in smem, coalesced copy-out
    const uint32_t cf = sbase;
    #pragma unroll
    for (int mi = 0; mi < 4; mi++) {
        #pragma unroll
        for (int ni = 0; ni < 4; ni++) {
            const int nl = wn + ni * 8 + 2 * (lane & 3);
            const int rl = wm + mi * 16 + (lane >> 2);
            float2 bv = *(const float2*)(bias + nb * 128 + nl);
            float2 p0 = make_float2(tanhf(acc[mi][ni][0] + bv.x),
                                    tanhf(acc[mi][ni][1] + bv.y));
            float2 p1 = make_float2(tanhf(acc[mi][ni][2] + bv.x),
                                    tanhf(acc[mi][ni][3] + bv.y));
            uint32_t a0 = cf + (uint32_t)rl * 512 + (uint32_t)nl * 4;
            asm volatile("st.shared.v2.f32 [%0], {%1, %2};"
                         :: "r"(a0), "f"(p0.x), "f"(p0.y) : "memory");
            asm volatile("st.shared.v2.f32 [%0], {%1, %2};"
                         :: "r"(a0 + 8 * 512), "f"(p1.x), "f"(p1.y) : "memory");
        }
    }
    __syncthreads();
    const uint32_t cf_off = cf - smem_u32(dsm);
    #pragma unroll
    for (int p = 0; p < 16; p++) {
        int idx = p * 256 + tid;
        int r = idx >> 5;
        int c4 = idx & 31;
        uint4 v = *(const uint4*)(dsm + cf_off + r * 512 + c4 * 16);
        *(uint4*)(Of + (size_t)(mb * 128 + r) * Ntot + nb * 128 + c4 * 4) = v;
    }
}

// ---------------------------------------------------------------------------
// FK chain (validated)
// ---------------------------------------------------------------------------
__global__ __launch_bounds__(256) void fk_kernel(
    const float* __restrict__ joints, float* __restrict__ out)
{
    int row = blockIdx.x * blockDim.x + threadIdx.x;
    if (row >= BATCH) return;
    const float4* jq = (const float4*)(joints + (size_t)row * 256);
    float* o = out + (size_t)row * 192;

    float r00 = 1, r01 = 0, r02 = 0;
    float r10 = 0, r11 = 1, r12 = 0;
    float r20 = 0, r21 = 0, r22 = 1;
    float t0 = 0, t1 = 0, t2 = 0;

    #pragma unroll 4
    for (int j = 0; j < 64; j++) {
        float4 q = jq[j];
        float w = q.x, x = q.y, y = q.z, z = q.w;
        float s = 2.0f / (w * w + x * x + y * y + z * z);

        float R00 = 1.0f - s * (y * y + z * z);
        float R01 = s * (x * y - z * w);
        float R02 = s * (x * z + y * w);
        float R10 = s * (x * y + z * w);
        float R11 = 1.0f - s * (x * x + z * z);
        float R12 = s * (y * z - x * w);
        float R20 = s * (x * z - y * w);
        float R21 = s * (y * z + x * w);
        float R22 = 1.0f - s * (x * x + y * y);

        float n00 = r00 * R00 + r01 * R10 + r02 * R20;
        float n01 = r00 * R01 + r01 * R11 + r02 * R21;
        float n02 = r00 * R02 + r01 * R12 + r02 * R22;
        float n10 = r10 * R00 + r11 * R10 + r12 * R20;
        float n11 = r10 * R01 + r11 * R11 + r12 * R21;
        float n12 = r10 * R02 + r11 * R12 + r12 * R22;
        float n20 = r20 * R00 + r21 * R10 + r22 * R20;
        float n21 = r20 * R01 + r21 * R11 + r22 * R21;
        float n22 = r20 * R02 + r21 * R12 + r22 * R22;

        float nt0 = r00 * R01 + r01 * R11 + r02 * R21 + t0;
        float nt1 = r10 * R01 + r11 * R11 + r12 * R21 + t1;
        float nt2 = r20 * R01 + r21 * R11 + r22 * R21 + t2;

        r00 = n00; r01 = n01; r02 = n02;
        r10 = n10; r11 = n11; r12 = n12;
        r20 = n20; r21 = n21; r22 = n22;
        t0 = nt0; t1 = nt1; t2 = nt2;

        o[j * 3 + 0] = t0;
        o[j * 3 + 1] = t1;
        o[j * 3 + 2] = t2;
    }
}

// ---------------------------------------------------------------------------
// Launch
// ---------------------------------------------------------------------------
extern "C" void kernel_launch(void* const* d_in, const int* in_sizes, int n_in,
                              void* d_out, int out_size)
{
    const float* x  = (const float*)d_in[0];
    const float* W1 = (const float*)d_in[1];
    const float* b1 = (const float*)d_in[2];
    const float* W2 = (const float*)d_in[3];
    const float* b2 = (const float*)d_in[4];
    const float* W3 = (const float*)d_in[5];
    const float* b3 = (const float*)d_in[6];
    const float* W4 = (const float*)d_in[7];
    const float* b4 = (const float*)d_in[8];
    float* out = (float*)d_out;

    __half *a0h, *a0l, *a1h, *a1l, *w2h, *w2l, *w3h, *w3l, *w4h, *w4l;
    float* jnt;
    cudaGetSymbolAddress((void**)&a0h, g_a0h);
    cudaGetSymbolAddress((void**)&a0l, g_a0l);
    cudaGetSymbolAddress((void**)&a1h, g_a1h);
    cudaGetSymbolAddress((void**)&a1l, g_a1l);
    cudaGetSymbolAddress((void**)&w2h, g_w2h);
    cudaGetSymbolAddress((void**)&w2l, g_w2l);
    cudaGetSymbolAddress((void**)&w3h, g_w3h);
    cudaGetSymbolAddress((void**)&w3l, g_w3l);
    cudaGetSymbolAddress((void**)&w4h, g_w4h);
    cudaGetSymbolAddress((void**)&w4l, g_w4l);
    cudaGetSymbolAddress((void**)&jnt, g_joints);

    const int SMEM64  = 4 * 24576 + 1024;   // 99328  -> 2 CTAs/SM
    const int SMEM128 = 3 * 32768 + 1024;   // 99328  -> 2 CTAs/SM
    cudaFuncSetAttribute(gemm64_kernel,  cudaFuncAttributeMaxDynamicSharedMemorySize, SMEM64);
    cudaFuncSetAttribute(gemm128_kernel, cudaFuncAttributeMaxDynamicSharedMemorySize, SMEM128);

    layer1_kernel<<<(BATCH * 128) / 256, 256>>>(x, W1, b1, a0h, a0l);
    wconv_kernel<<<(1024 * 128) / 256, 256>>>(W2, w2h, w2l, 1024);
    wconv_kernel<<<(1024 * 128) / 256, 256>>>(W3, w3h, w3l, 1024);
    wconv_kernel<<<(256 * 128) / 256, 256>>>(W4, w4h, w4l, 256);

    // L2: a0 @ W2 -> a1 (leaky), 2048 CTAs
    gemm64_kernel<<<dim3(16, 128), 256, SMEM64>>>(a0h, a0l, w2h, w2l, b2,
                                                  a1h, a1l, 1024);
    // L3: a1 @ W3 -> a0 (leaky)
    gemm64_kernel<<<dim3(16, 128), 256, SMEM64>>>(a1h, a1l, w3h, w3l, b3,
                                                  a0h, a0l, 1024);
    // L4: a0 @ W4 -> joints (tanh, fp32)
    gemm128_kernel<<<dim3(2, 128), 256, SMEM128>>>(a0h, a0l, w4h, w4l, b4,
                                                   jnt, 256);
    fk_kernel<<<BATCH / 256, 256>>>(jnt, out);
}

// round 8
// speedup vs baseline: 1.0887x; 1.0887x over previous
#include <cuda_runtime.h>
#include <cuda_fp16.h>
#include <math.h>
#include <stdint.h>

// ---------------------------------------------------------------------------
// fkopt_net round 8 (= round 7 resubmit, infra failure):
// 128x128 / BK=32 / 3-stage / 2 CTAs/SM GEMM with per-stage empty mbarriers
// instead of per-chunk __syncthreads (consumer warps decoupled).
// Only change vs round 7: plain mbarrier.arrive form (proven syntax).
// ---------------------------------------------------------------------------

#define BATCH 16384
#define KDIM  1024
#define NEG_SLOPE 0.01f

__device__ __align__(1024) __half g_a0h[BATCH * KDIM];
__device__ __align__(1024) __half g_a0l[BATCH * KDIM];
__device__ __align__(1024) __half g_a1h[BATCH * KDIM];
__device__ __align__(1024) __half g_a1l[BATCH * KDIM];
__device__ __align__(1024) __half g_w2h[KDIM * KDIM];
__device__ __align__(1024) __half g_w2l[KDIM * KDIM];
__device__ __align__(1024) __half g_w3h[KDIM * KDIM];
__device__ __align__(1024) __half g_w3l[KDIM * KDIM];
__device__ __align__(1024) __half g_w4h[256 * KDIM];
__device__ __align__(1024) __half g_w4l[256 * KDIM];
__device__ __align__(1024) float g_joints[BATCH * 256];

// ---------------- PTX helpers ----------------------------------------------
__device__ __forceinline__ uint32_t smem_u32(const void* p) {
    uint32_t a;
    asm("{ .reg .u64 t; cvta.to.shared.u64 t, %1; cvt.u32.u64 %0, t; }"
        : "=r"(a) : "l"(p));
    return a;
}
__device__ __forceinline__ void mbar_init(uint32_t a, uint32_t c) {
    asm volatile("mbarrier.init.shared.b64 [%0], %1;" :: "r"(a), "r"(c) : "memory");
}
__device__ __forceinline__ void mbar_expect(uint32_t a, uint32_t tx) {
    asm volatile("mbarrier.arrive.expect_tx.shared.b64 _, [%0], %1;"
                 :: "r"(a), "r"(tx) : "memory");
}
__device__ __forceinline__ void mbar_arrive(uint32_t a) {
    asm volatile("mbarrier.arrive.shared.b64 _, [%0];" :: "r"(a) : "memory");
}
__device__ __forceinline__ void mbar_wait(uint32_t a, uint32_t ph) {
    asm volatile(
        "{\n\t.reg .pred P;\n\t"
        "WL_%=:\n\t"
        "mbarrier.try_wait.parity.acquire.cta.shared::cta.b64 P, [%0], %1, 0x989680;\n\t"
        "@P bra.uni WD_%=;\n\t"
        "bra.uni WL_%=;\n\t"
        "WD_%=:\n\t}"
        :: "r"(a), "r"(ph) : "memory");
}
__device__ __forceinline__ void bulk_g2s(uint32_t dst, const void* src,
                                         uint32_t bytes, uint32_t mbar) {
    asm volatile(
        "cp.async.bulk.shared::cluster.global.mbarrier::complete_tx::bytes "
        "[%0], [%1], %2, [%3];"
        :: "r"(dst), "l"(src), "r"(bytes), "r"(mbar) : "memory");
}
__device__ __forceinline__ void bulk_s2g(void* dst, uint32_t src, uint32_t bytes) {
    asm volatile(
        "cp.async.bulk.global.shared::cta.bulk_group [%0], [%1], %2;"
        :: "l"(dst), "r"(src), "r"(bytes) : "memory");
}

#define LDSM4(r, a)                                                              \
    asm volatile("ldmatrix.sync.aligned.m8n8.x4.shared.b16 {%0,%1,%2,%3}, [%4];" \
                 : "=r"((r)[0]), "=r"((r)[1]), "=r"((r)[2]), "=r"((r)[3])        \
                 : "r"(a))
#define LDSM2(r, a)                                                              \
    asm volatile("ldmatrix.sync.aligned.m8n8.x2.shared.b16 {%0,%1}, [%2];"       \
                 : "=r"((r)[0]), "=r"((r)[1]) : "r"(a))
#define MMA16816(d, a, b)                                                        \
    asm volatile("mma.sync.aligned.m16n8k16.row.col.f32.f16.f16.f32 "            \
                 "{%0,%1,%2,%3}, {%4,%5,%6,%7}, {%8,%9}, {%0,%1,%2,%3};"         \
                 : "+f"((d)[0]), "+f"((d)[1]), "+f"((d)[2]), "+f"((d)[3])        \
                 : "r"((a)[0]), "r"((a)[1]), "r"((a)[2]), "r"((a)[3]),           \
                   "r"((b)[0]), "r"((b)[1]))

// tile byte-offset swizzle: off = row*64 + col*2 (32 fp16 cols per row)
__device__ __forceinline__ uint32_t swz(uint32_t off) {
    return off ^ (((off >> 7) & 3u) << 4);
}
__device__ __forceinline__ void split_h(float v, __half& h, __half& l) {
    h = __float2half_rn(v);
    l = __float2half_rn(v - __half2float(h));
}
__device__ __forceinline__ uint32_t pack_h2(__half a, __half b) {
    return ((uint32_t)__half_as_ushort(b) << 16) | (uint32_t)__half_as_ushort(a);
}

// ---------------------------------------------------------------------------
// Layer 1 producer (validated)
// ---------------------------------------------------------------------------
__global__ __launch_bounds__(256) void layer1_kernel(
    const float* __restrict__ x, const float* __restrict__ W1,
    const float* __restrict__ b1,
    __half* __restrict__ Ohi, __half* __restrict__ Olo)
{
    int idx = blockIdx.x * 256 + threadIdx.x;
    int n0 = (idx & 127) * 8;
    int m  = idx >> 7;
    float x0 = __ldg(x + m * 3 + 0);
    float x1 = __ldg(x + m * 3 + 1);
    float x2 = __ldg(x + m * 3 + 2);

    uint32_t hw[4], lw[4];
    #pragma unroll
    for (int p = 0; p < 4; p++) {
        int n = n0 + 2 * p;
        float v0 = __ldg(b1 + n) + x0 * __ldg(W1 + n) +
                   x1 * __ldg(W1 + 1024 + n) + x2 * __ldg(W1 + 2048 + n);
        float v1 = __ldg(b1 + n + 1) + x0 * __ldg(W1 + n + 1) +
                   x1 * __ldg(W1 + 1024 + n + 1) + x2 * __ldg(W1 + 2048 + n + 1);
        v0 = (v0 >= 0.0f) ? v0 : NEG_SLOPE * v0;
        v1 = (v1 >= 0.0f) ? v1 : NEG_SLOPE * v1;
        __half h0, l0, h1, l1;
        split_h(v0, h0, l0); split_h(v1, h1, l1);
        hw[p] = pack_h2(h0, h1);
        lw[p] = pack_h2(l0, l1);
    }
    size_t tile = (size_t)(m >> 7) * 32 + (n0 >> 5);
    uint32_t off = swz((uint32_t)(m & 127) * 64 + (uint32_t)(n0 & 31) * 2);
    *(uint4*)((char*)Ohi + tile * 8192 + off) = make_uint4(hw[0], hw[1], hw[2], hw[3]);
    *(uint4*)((char*)Olo + tile * 8192 + off) = make_uint4(lw[0], lw[1], lw[2], lw[3]);
}

// ---------------------------------------------------------------------------
// Weight convert+transpose producer (validated)
// ---------------------------------------------------------------------------
__global__ __launch_bounds__(256) void wconv_kernel(
    const float* __restrict__ W,
    __half* __restrict__ Ohi, __half* __restrict__ Olo, int N)
{
    int idx = blockIdx.x * 256 + threadIdx.x;
    int n  = idx % N;
    int k0 = (idx / N) * 8;
    uint32_t hw[4], lw[4];
    #pragma unroll
    for (int p = 0; p < 4; p++) {
        float v0 = __ldg(W + (size_t)(k0 + 2 * p) * N + n);
        float v1 = __ldg(W + (size_t)(k0 + 2 * p + 1) * N + n);
        __half h0, l0, h1, l1;
        split_h(v0, h0, l0); split_h(v1, h1, l1);
        hw[p] = pack_h2(h0, h1);
        lw[p] = pack_h2(l0, l1);
    }
    size_t tile = (size_t)(n >> 7) * 32 + (k0 >> 5);
    uint32_t off = swz((uint32_t)(n & 127) * 64 + (uint32_t)(k0 & 31) * 2);
    *(uint4*)((char*)Ohi + tile * 8192 + off) = make_uint4(hw[0], hw[1], hw[2], hw[3]);
    *(uint4*)((char*)Olo + tile * 8192 + off) = make_uint4(lw[0], lw[1], lw[2], lw[3]);
}

// ---------------------------------------------------------------------------
// GEMM: C[16384, Ntot] = act(A @ W + bias), fp16x3 mma.sync.
// CTA tile 128x128, BK=32 (32 chunks), 3-stage x 32KB pipeline, 2 CTAs/SM.
// Consumer warps decoupled via per-stage empty mbarriers (count=8).
// MODE 0: leaky + tiled hi/lo out. MODE 1: tanh + fp32 row-major out.
// ---------------------------------------------------------------------------
template <int MODE>
__global__ __launch_bounds__(256, 2) void gemm_kernel(
    const __half* __restrict__ Ahg, const __half* __restrict__ Alg,
    const __half* __restrict__ Bhg, const __half* __restrict__ Blg,
    const float* __restrict__ bias,
    __half* __restrict__ Ohi, __half* __restrict__ Olo,
    float* __restrict__ Of, int Ntot)
{
    constexpr int NC = 32;                  // K=1024 / BK=32
    constexpr uint32_t STAGE = 32768;
    __shared__ __align__(8) uint64_t bar_full[3], bar_empty[3];
    extern __shared__ char dsm[];
    const uint32_t sbase = (smem_u32(dsm) + 1023) & ~1023u;

    const int tid = threadIdx.x, lane = tid & 31, wid = tid >> 5;
    const int mb = blockIdx.y, nb = blockIdx.x;
    const int wm = (wid & 1) * 64;
    const int wn = (wid >> 1) * 32;

    if (tid == 0) {
        for (int s = 0; s < 3; s++) {
            mbar_init(smem_u32(&bar_full[s]), 1);
            mbar_init(smem_u32(&bar_empty[s]), 8);   // 8 consumer warps
        }
    }
    __syncthreads();

    const char* Ah = (const char*)Ahg + (size_t)mb * 32 * 8192;
    const char* Al = (const char*)Alg + (size_t)mb * 32 * 8192;
    const char* Bh = (const char*)Bhg + (size_t)nb * 32 * 8192;
    const char* Bl = (const char*)Blg + (size_t)nb * 32 * 8192;

    // prologue: stages 0,1
    if (tid == 0) {
        #pragma unroll
        for (int c = 0; c < 2; c++) {
            uint32_t fb = smem_u32(&bar_full[c]);
            mbar_expect(fb, STAGE);
            uint32_t d = sbase + c * STAGE;
            bulk_g2s(d,         Ah + (size_t)c * 8192, 8192, fb);
            bulk_g2s(d + 8192,  Al + (size_t)c * 8192, 8192, fb);
            bulk_g2s(d + 16384, Bh + (size_t)c * 8192, 8192, fb);
            bulk_g2s(d + 24576, Bl + (size_t)c * 8192, 8192, fb);
        }
    }

    // per-lane ldmatrix addressing (within an 8KB tile)
    const int rowA = wm + (lane & 15);
    const uint32_t xa = (rowA >> 1) & 3;
    const uint32_t offA = (uint32_t)rowA * 64;
    const uint32_t cA[2] = { (((uint32_t)(lane >> 4) + 0) ^ xa) * 16,
                             (((uint32_t)(lane >> 4) + 2) ^ xa) * 16 };
    const int rowB = wn + (lane & 7);
    const uint32_t xb = (rowB >> 1) & 3;
    const uint32_t offB = (uint32_t)rowB * 64;
    const uint32_t cB[2] = { ((((uint32_t)(lane >> 3) & 1) + 0) ^ xb) * 16,
                             ((((uint32_t)(lane >> 3) & 1) + 2) ^ xb) * 16 };

    float acc[4][4][4];
    #pragma unroll
    for (int i = 0; i < 4; i++)
        #pragma unroll
        for (int j = 0; j < 4; j++)
            #pragma unroll
            for (int r = 0; r < 4; r++) acc[i][j][r] = 0.0f;

    #pragma unroll 1
    for (int c = 0; c < NC; c++) {
        // producer: issue chunk j = c+2 into stage j%3 once its previous
        // occupant (chunk j-3) has been released by all 8 warps.
        if (tid == 0 && c + 2 < NC) {
            int j = c + 2;
            int s = j % 3;
            if (j >= 3) mbar_wait(smem_u32(&bar_empty[s]), (j / 3 - 1) & 1);
            uint32_t fb = smem_u32(&bar_full[s]);
            mbar_expect(fb, STAGE);
            uint32_t d = sbase + s * STAGE;
            bulk_g2s(d,         Ah + (size_t)j * 8192, 8192, fb);
            bulk_g2s(d + 8192,  Al + (size_t)j * 8192, 8192, fb);
            bulk_g2s(d + 16384, Bh + (size_t)j * 8192, 8192, fb);
            bulk_g2s(d + 24576, Bl + (size_t)j * 8192, 8192, fb);
        }
        mbar_wait(smem_u32(&bar_full[c % 3]), (c / 3) & 1);

        const uint32_t sb = sbase + (c % 3) * STAGE;
        #pragma unroll
        for (int kk = 0; kk < 2; kk++) {
            const uint32_t ca = cA[kk], cb = cB[kk];
            uint32_t ah[4][4], al[4][4];
            #pragma unroll
            for (int mi = 0; mi < 4; mi++) {
                LDSM4(ah[mi], sb + offA + mi * 1024 + ca);
                LDSM4(al[mi], sb + 8192 + offA + mi * 1024 + ca);
            }
            #pragma unroll
            for (int ni = 0; ni < 4; ni++) {
                uint32_t bh[2], bl[2];
                LDSM2(bh, sb + 16384 + offB + ni * 512 + cb);
                LDSM2(bl, sb + 24576 + offB + ni * 512 + cb);
                #pragma unroll
                for (int mi = 0; mi < 4; mi++) MMA16816(acc[mi][ni], ah[mi], bh);
                #pragma unroll
                for (int mi = 0; mi < 4; mi++) MMA16816(acc[mi][ni], al[mi], bh);
                #pragma unroll
                for (int mi = 0; mi < 4; mi++) MMA16816(acc[mi][ni], ah[mi], bl);
            }
        }
        // release this stage (smem reads all issued by this warp)
        if (lane == 0) mbar_arrive(smem_u32(&bar_empty[c % 3]));
    }

    __syncthreads();   // all warps done with stage smem before reuse

    // ---------------- epilogue ----------------
    if (MODE == 0) {
        const uint32_t chi = sbase, clo = sbase + 32768;
        #pragma unroll
        for (int mi = 0; mi < 4; mi++) {
            #pragma unroll
            for (int ni = 0; ni < 4; ni++) {
                const int nl = wn + ni * 8 + 2 * (lane & 3);
                const int rl = wm + mi * 16 + (lane >> 2);
                float2 bv = *(const float2*)(bias + nb * 128 + nl);
                float v0 = acc[mi][ni][0] + bv.x;
                float v1 = acc[mi][ni][1] + bv.y;
                float v2 = acc[mi][ni][2] + bv.x;
                float v3 = acc[mi][ni][3] + bv.y;
                v0 = (v0 >= 0.0f) ? v0 : NEG_SLOPE * v0;
                v1 = (v1 >= 0.0f) ? v1 : NEG_SLOPE * v1;
                v2 = (v2 >= 0.0f) ? v2 : NEG_SLOPE * v2;
                v3 = (v3 >= 0.0f) ? v3 : NEG_SLOPE * v3;
                __half h0, l0, h1, l1, h2, l2, h3, l3;
                split_h(v0, h0, l0); split_h(v1, h1, l1);
                split_h(v2, h2, l2); split_h(v3, h3, l3);
                const uint32_t tb = (uint32_t)(nl >> 5) * 8192;
                const uint32_t off = swz((uint32_t)rl * 64 + (uint32_t)(nl & 31) * 2);
                asm volatile("st.shared.b32 [%0], %1;" :: "r"(chi + tb + off),       "r"(pack_h2(h0, h1)) : "memory");
                asm volatile("st.shared.b32 [%0], %1;" :: "r"(chi + tb + off + 512), "r"(pack_h2(h2, h3)) : "memory");
                asm volatile("st.shared.b32 [%0], %1;" :: "r"(clo + tb + off),       "r"(pack_h2(l0, l1)) : "memory");
                asm volatile("st.shared.b32 [%0], %1;" :: "r"(clo + tb + off + 512), "r"(pack_h2(l2, l3)) : "memory");
            }
        }
        __syncthreads();
        if (tid == 0) {
            asm volatile("fence.proxy.async;" ::: "memory");
            const size_t tbase = (size_t)mb * 32 + (size_t)nb * 4;
            #pragma unroll
            for (int t = 0; t < 4; t++) {
                bulk_s2g((char*)Ohi + (tbase + t) * 8192, chi + t * 8192, 8192);
                bulk_s2g((char*)Olo + (tbase + t) * 8192, clo + t * 8192, 8192);
            }
            asm volatile("cp.async.bulk.commit_group;" ::: "memory");
            asm volatile("cp.async.bulk.wait_group 0;" ::: "memory");
        }
    } else {
        const uint32_t cf = sbase;
        #pragma unroll
        for (int mi = 0; mi < 4; mi++) {
            #pragma unroll
            for (int ni = 0; ni < 4; ni++) {
                const int nl = wn + ni * 8 + 2 * (lane & 3);
                const int rl = wm + mi * 16 + (lane >> 2);
                float2 bv = *(const float2*)(bias + nb * 128 + nl);
                float2 p0 = make_float2(tanhf(acc[mi][ni][0] + bv.x),
                                        tanhf(acc[mi][ni][1] + bv.y));
                float2 p1 = make_float2(tanhf(acc[mi][ni][2] + bv.x),
                                        tanhf(acc[mi][ni][3] + bv.y));
                uint32_t a0 = cf + (uint32_t)rl * 512 + (uint32_t)nl * 4;
                asm volatile("st.shared.v2.f32 [%0], {%1, %2};"
                             :: "r"(a0), "f"(p0.x), "f"(p0.y) : "memory");
                asm volatile("st.shared.v2.f32 [%0], {%1, %2};"
                             :: "r"(a0 + 8 * 512), "f"(p1.x), "f"(p1.y) : "memory");
            }
        }
        __syncthreads();
        const uint32_t cf_off = cf - smem_u32(dsm);
        #pragma unroll
        for (int p = 0; p < 16; p++) {
            int idx = p * 256 + tid;
            int r = idx >> 5;
            int c4 = idx & 31;
            uint4 v = *(const uint4*)(dsm + cf_off + r * 512 + c4 * 16);
            *(uint4*)(Of + (size_t)(mb * 128 + r) * Ntot + nb * 128 + c4 * 4) = v;
        }
    }
}

// ---------------------------------------------------------------------------
// FK chain (validated)
// ---------------------------------------------------------------------------
__global__ __launch_bounds__(256) void fk_kernel(
    const float* __restrict__ joints, float* __restrict__ out)
{
    int row = blockIdx.x * blockDim.x + threadIdx.x;
    if (row >= BATCH) return;
    const float4* jq = (const float4*)(joints + (size_t)row * 256);
    float* o = out + (size_t)row * 192;

    float r00 = 1, r01 = 0, r02 = 0;
    float r10 = 0, r11 = 1, r12 = 0;
    float r20 = 0, r21 = 0, r22 = 1;
    float t0 = 0, t1 = 0, t2 = 0;

    #pragma unroll 4
    for (int j = 0; j < 64; j++) {
        float4 q = jq[j];
        float w = q.x, x = q.y, y = q.z, z = q.w;
        float s = 2.0f / (w * w + x * x + y * y + z * z);

        float R00 = 1.0f - s * (y * y + z * z);
        float R01 = s * (x * y - z * w);
        float R02 = s * (x * z + y * w);
        float R10 = s * (x * y + z * w);
        float R11 = 1.0f - s * (x * x + z * z);
        float R12 = s * (y * z - x * w);
        float R20 = s * (x * z - y * w);
        float R21 = s * (y * z + x * w);
        float R22 = 1.0f - s * (x * x + y * y);

        float n00 = r00 * R00 + r01 * R10 + r02 * R20;
        float n01 = r00 * R01 + r01 * R11 + r02 * R21;
        float n02 = r00 * R02 + r01 * R12 + r02 * R22;
        float n10 = r10 * R00 + r11 * R10 + r12 * R20;
        float n11 = r10 * R01 + r11 * R11 + r12 * R21;
        float n12 = r10 * R02 + r11 * R12 + r12 * R22;
        float n20 = r20 * R00 + r21 * R10 + r22 * R20;
        float n21 = r20 * R01 + r21 * R11 + r22 * R21;
        float n22 = r20 * R02 + r21 * R12 + r22 * R22;

        float nt0 = r00 * R01 + r01 * R11 + r02 * R21 + t0;
        float nt1 = r10 * R01 + r11 * R11 + r12 * R21 + t1;
        float nt2 = r20 * R01 + r21 * R11 + r22 * R21 + t2;

        r00 = n00; r01 = n01; r02 = n02;
        r10 = n10; r11 = n11; r12 = n12;
        r20 = n20; r21 = n21; r22 = n22;
        t0 = nt0; t1 = nt1; t2 = nt2;

        o[j * 3 + 0] = t0;
        o[j * 3 + 1] = t1;
        o[j * 3 + 2] = t2;
    }
}

// ---------------------------------------------------------------------------
// Launch — GEMM L2 placed at launch index 3 so ncu captures it.
// ---------------------------------------------------------------------------
extern "C" void kernel_launch(void* const* d_in, const int* in_sizes, int n_in,
                              void* d_out, int out_size)
{
    const float* x  = (const float*)d_in[0];
    const float* W1 = (const float*)d_in[1];
    const float* b1 = (const float*)d_in[2];
    const float* W2 = (const float*)d_in[3];
    const float* b2 = (const float*)d_in[4];
    const float* W3 = (const float*)d_in[5];
    const float* b3 = (const float*)d_in[6];
    const float* W4 = (const float*)d_in[7];
    const float* b4 = (const float*)d_in[8];
    float* out = (float*)d_out;

    __half *a0h, *a0l, *a1h, *a1l, *w2h, *w2l, *w3h, *w3l, *w4h, *w4l;
    float* jnt;
    cudaGetSymbolAddress((void**)&a0h, g_a0h);
    cudaGetSymbolAddress((void**)&a0l, g_a0l);
    cudaGetSymbolAddress((void**)&a1h, g_a1h);
    cudaGetSymbolAddress((void**)&a1l, g_a1l);
    cudaGetSymbolAddress((void**)&w2h, g_w2h);
    cudaGetSymbolAddress((void**)&w2l, g_w2l);
    cudaGetSymbolAddress((void**)&w3h, g_w3h);
    cudaGetSymbolAddress((void**)&w3l, g_w3l);
    cudaGetSymbolAddress((void**)&w4h, g_w4h);
    cudaGetSymbolAddress((void**)&w4l, g_w4l);
    cudaGetSymbolAddress((void**)&jnt, g_joints);

    const int SMEM = 3 * 32768 + 1024;   // 99328 -> 2 CTAs/SM
    cudaFuncSetAttribute(gemm_kernel<0>, cudaFuncAttributeMaxDynamicSharedMemorySize, SMEM);
    cudaFuncSetAttribute(gemm_kernel<1>, cudaFuncAttributeMaxDynamicSharedMemorySize, SMEM);

    // idx 0..2: producers needed by L2 (+W3 early)
    layer1_kernel<<<(BATCH * 128) / 256, 256>>>(x, W1, b1, a0h, a0l);
    wconv_kernel<<<(1024 * 128) / 256, 256>>>(W2, w2h, w2l, 1024);
    wconv_kernel<<<(1024 * 128) / 256, 256>>>(W3, w3h, w3l, 1024);

    // idx 3: L2 GEMM (profiled slot)
    gemm_kernel<0><<<dim3(8, 128), 256, SMEM>>>(a0h, a0l, w2h, w2l, b2,
                                                a1h, a1l, nullptr, 1024);
    // idx 4: W4 producer
    wconv_kernel<<<(256 * 128) / 256, 256>>>(W4, w4h, w4l, 256);

    // idx 5: L3
    gemm_kernel<0><<<dim3(8, 128), 256, SMEM>>>(a1h, a1l, w3h, w3l, b3,
                                                a0h, a0l, nullptr, 1024);
    // idx 6: L4
    gemm_kernel<1><<<dim3(2, 128), 256, SMEM>>>(a0h, a0l, w4h, w4l, b4,
                                                nullptr, nullptr, jnt, 256);
    // idx 7: FK
    fk_kernel<<<BATCH / 256, 256>>>(jnt, out);
}